// round 1
// baseline (speedup 1.0000x reference)
#include <cuda_runtime.h>

// FFM pairwise interactions:
//   inputs: (B=4096, N*N=400, E=64) fp32, viewed as v[b, j, i, e]
//   output: (B, 1, P=190, E) fp32, out[b, 0, p, e] = v[b, jj, ii, e] * v[b, ii, jj, e]
// with (ii, jj) = upper-triangle pairs i<j in triu_indices order.
//
// Pure HBM-streaming: ~398 MB read + ~199 MB write, no reuse.

constexpr int N_FIELDS = 20;
constexpr int EMBED    = 64;
constexpr int NPAIRS   = 190;              // N*(N-1)/2
constexpr int QUADS    = EMBED / 4;        // float4 per row = 16

__global__ void __launch_bounds__(256)
ffm_pair_kernel(const float4* __restrict__ in, float4* __restrict__ out, int total)
{
    int t = blockIdx.x * blockDim.x + threadIdx.x;
    if (t >= total) return;

    int q  = t & (QUADS - 1);   // quad within E
    int bp = t >> 4;            // (b * NPAIRS + p)
    int p  = bp % NPAIRS;       // compiler turns both into magic-mul
    int b  = bp / NPAIRS;

    // Recover (i, j) from triu pair index p (i ascending, j = i+1..N-1).
    // At most 19 iterations; a warp spans only 2 distinct p values.
    int i = 0, rem = p;
    #pragma unroll 1
    while (rem >= N_FIELDS - 1 - i) { rem -= N_FIELDS - 1 - i; ++i; }
    int j = i + 1 + rem;

    const long base = (long)b * (N_FIELDS * N_FIELDS) * QUADS;
    float4 a = __ldg(&in[base + (long)(j * N_FIELDS + i) * QUADS + q]); // v[b, j, i, :]
    float4 c = __ldg(&in[base + (long)(i * N_FIELDS + j) * QUADS + q]); // v[b, i, j, :]

    float4 r;
    r.x = a.x * c.x;
    r.y = a.y * c.y;
    r.z = a.z * c.z;
    r.w = a.w * c.w;

    // Output flat float4 index == t  (b*P*16 + p*16 + q)
    out[t] = r;
}

extern "C" void kernel_launch(void* const* d_in, const int* in_sizes, int n_in,
                              void* d_out, int out_size)
{
    const float4* in  = (const float4*)d_in[0];
    float4*       out = (float4*)d_out;

    // total float4 outputs = out_size / 4
    int total = out_size / 4;   // 4096 * 190 * 16 = 12,441,600
    int threads = 256;
    int blocks = (total + threads - 1) / threads;
    ffm_pair_kernel<<<blocks, threads>>>(in, out, total);
}